// round 11
// baseline (speedup 1.0000x reference)
#include <cuda_runtime.h>
#include <cuda_bf16.h>

// preds: [128, 4096, 50] float32 -> 26,214,400 elems (d_in[0])
// gt:    [128, 4096]     int32   ->    524,288 elems (d_in[1])
// out:   scalar float32
//
// SINGLE-PASS v2. preds is read EXACTLY ONCE (the two-phase designs re-touch
// most cache lines for the row windows -- that duplicated scattered DRAM
// traffic is the tax this removes). Hot-loop overhead vs R7 cut ~2x:
//  - rowcode kernel precomputes per-row byte (q, or 50 if unvoiced) + voiced
//    count partials -> no per-iter IDIV, no g!=100 tests, no count FMAs
//  - 2D smem table tab2[n][q] (50x51, col 50 == 0): per-element dot is one
//    unpredicated LDS + FFMA from a static base (thread's bin n is constant)
// Tile mapping (2 rows = 25 float4s, stride divisible by 25) as validated R7.

#define NF4       6553600u
#define ROWS      524288u
#define NBINS     50
#define TQ        51            // table cols: q=0..49 real, q=50 => zero

#define SP_BLOCKS  1175u        // 47*25 -> NTHREADS % 25 == 0; <=1184 one wave
#define SP_THREADS 256u
#define NTHREADS   (SP_BLOCKS * SP_THREADS)   // 300800
#define TILE_STR   (NTHREADS / 25u)           // 12032

#define RC_BLOCKS  2048u
#define RC_THREADS 256u

__device__ unsigned char g_rowcode[ROWS];
__device__ int           g_cnt2[RC_BLOCKS];
__device__ float         g_part[SP_BLOCKS];
__device__ unsigned      g_done;

__device__ __forceinline__ float gk(int i) {
    const float K0 = 2.6386456e-4f;
    const float K1 = 0.10645078f;
    const float K2 = 0.78657072f;
    return (i == 2) ? K2 : ((i == 1 || i == 3) ? K1 : K0);
}

// ---------------------------------------------------------------------------
// Kernel 0: per-row code byte + voiced-count partials.
// ---------------------------------------------------------------------------
__global__ __launch_bounds__(RC_THREADS) void rowcode_kernel(
    const int* __restrict__ gt)
{
    const unsigned r = blockIdx.x * RC_THREADS + threadIdx.x;
    int g = gt[r];
    int q = (g > 50) ? min((g - 50) / 6, NBINS - 1) : 0;
    int voiced = (g != 100);
    g_rowcode[r] = (unsigned char)(voiced ? q : 50);

    __shared__ int sc[RC_THREADS];
    int tid = threadIdx.x;
    sc[tid] = voiced;
    __syncthreads();
    #pragma unroll
    for (int o = RC_THREADS / 2; o > 0; o >>= 1) {
        if (tid < o) sc[tid] += sc[tid + o];
        __syncthreads();
    }
    if (tid == 0) g_cnt2[blockIdx.x] = sc[0];
}

// ---------------------------------------------------------------------------
// Kernel 1: single streaming pass (softplus + dot), last block finalizes.
// ---------------------------------------------------------------------------
__global__ __launch_bounds__(SP_THREADS, 8) void pitchloss_kernel(
    const float* __restrict__ preds, float* __restrict__ out)
{
    // tab2[n*TQ + q] = blurred-one-hot target value at bin n for center q.
    __shared__ float tab2[NBINS * TQ];          // 10.2 KB
    const int tid = threadIdx.x;
    for (int idx = tid; idx < NBINS * TQ; idx += SP_THREADS) {
        int n = idx / TQ, q = idx % TQ;
        float t = 0.0f;
        if (q < NBINS) {
            #pragma unroll
            for (int i = 0; i < 5; i++) {
                int m  = n + i - 2;
                int mm = (m < 0) ? -m : ((m > NBINS - 1) ? (2*(NBINS-1) - m) : m);
                if (mm == q) t += gk(i);
            }
        }
        tab2[idx] = t;
    }
    __syncthreads();

    const unsigned gtid = blockIdx.x * SP_THREADS + tid;
    const unsigned jj   = gtid % 25u;
    unsigned       T    = gtid / 25u;           // current tile (2 rows)
    const int eloc  = 4 * (int)jj;              // 0..96
    const int a_sh  = (eloc >= 50) ? 8 : 0;     // byte shift for elems 0,1
    const int b_sh  = (eloc >= 48) ? 8 : 0;     // byte shift for elems 2,3
    const int na    = eloc - ((eloc >= 50) ? 50 : 0);
    const int nb    = (eloc == 48) ? 0 : (na + 2);
    const float* tabA = &tab2[na * TQ];
    const float* tabB = &tab2[nb * TQ];
    const unsigned short* rp = reinterpret_cast<const unsigned short*>(g_rowcode);

    float acc = 0.0f, dot = 0.0f;
    const float4* p4 = reinterpret_cast<const float4*>(preds);

    for (unsigned i = gtid; i < NF4; i += NTHREADS, T += TILE_STR) {
        float4 v = p4[i];
        unsigned u = (unsigned)__ldg(rp + T);   // codes for rows 2T, 2T+1
        int ca = (u >> a_sh) & 0xFF;
        int cb = (u >> b_sh) & 0xFF;
        float wa = (ca != 50) ? 1.0f : 0.0f;
        float wb = (cb != 50) ? 1.0f : 0.0f;

        dot = fmaf(v.x, tabA[ca],      dot);
        dot = fmaf(v.y, tabA[ca + TQ], dot);
        dot = fmaf(v.z, tabB[cb],      dot);
        dot = fmaf(v.w, tabB[cb + TQ], dot);

        float e0 = wa * __expf(v.x);
        float e1 = wa * __expf(v.y);
        float e2 = wb * __expf(v.z);
        float e3 = wb * __expf(v.w);
        float pr = 1.0f + e0;
        pr = fmaf(pr, e1, pr);
        pr = fmaf(pr, e2, pr);
        pr = fmaf(pr, e3, pr);
        acc += __log2f(pr);
    }

    // ---------------- block reduction -------------------------------------
    const float LN2 = 0.69314718055994530942f;
    float part = fmaf(LN2, acc, -dot);

    __shared__ float sp[SP_THREADS];
    sp[tid] = part;
    __syncthreads();
    #pragma unroll
    for (int o = SP_THREADS / 2; o > 0; o >>= 1) {
        if (tid < o) sp[tid] += sp[tid + o];
        __syncthreads();
    }

    __shared__ bool s_last;
    if (tid == 0) {
        g_part[blockIdx.x] = sp[0];
        __threadfence();
        unsigned t = atomicAdd(&g_done, 1u);
        s_last = (t == SP_BLOCKS - 1);
    }
    __syncthreads();

    // ---------------- last block: deterministic ordered finalize ----------
    if (s_last) {
        float a = 0.0f;
        for (unsigned j = tid; j < SP_BLOCKS; j += SP_THREADS) a += g_part[j];
        int c = 0;
        for (unsigned j = tid; j < RC_BLOCKS; j += SP_THREADS) c += g_cnt2[j];
        __shared__ int scc[SP_THREADS];
        sp[tid] = a; scc[tid] = c;
        __syncthreads();
        #pragma unroll
        for (int o = SP_THREADS / 2; o > 0; o >>= 1) {
            if (tid < o) { sp[tid] += sp[tid + o]; scc[tid] += scc[tid + o]; }
            __syncthreads();
        }
        if (tid == 0) {
            out[0] = sp[0] / (50.0f * (float)scc[0]);
            g_done = 0;   // reset for next (graph-replayed) launch
        }
    }
}

extern "C" void kernel_launch(void* const* d_in, const int* in_sizes, int n_in,
                              void* d_out, int out_size)
{
    const float* preds = (const float*)d_in[0];
    const int*   gt    = (const int*)d_in[1];
    float* out = (float*)d_out;

    rowcode_kernel<<<RC_BLOCKS, RC_THREADS>>>(gt);
    pitchloss_kernel<<<SP_BLOCKS, SP_THREADS>>>(preds, out);
}

// round 14
// speedup vs baseline: 1.1633x; 1.1633x over previous
#include <cuda_runtime.h>
#include <cuda_bf16.h>

// preds: [128, 4096, 50] float32 -> 26,214,400 elems (d_in[0])
// gt:    [128, 4096]     int32   ->    524,288 elems (d_in[1])
// out:   scalar float32
//
// loss = [ LN2*(sum_all log2(1+exp(p)) - sum_{unvoiced} log2(1+exp(p)))
//          - sum_{voiced} p.tgt ] / (50 * n_voiced)
//
// R6 champion frame; phase A uses FLOAT2-ALIGNED window pairs (rows are 200B
// apart -> 8B-aligned ALWAYS; 16B only for even rows -- R12's float4 crash):
//  - window [2c2, 2c2+5], c2 = max(q-2,0)>>1, covers [q-2,q+2]; q <= 24
//    (gt <= 199) -> never crosses row end, never hits the upper reflect edge
//  - 6 target values depend only on up = (q<=2 ? q : 3+((q-2)&1)) in 0..4:
//    rows 0..2 = exact low-edge (reflect baked in), rows 3..4 = interior
//    kernel centered at window pos 2/3. 5x8 table -> <=2-way LDS conflicts.

#define NF4       6553600u
#define ROWS      524288u
#define NBINS     50

#define SP_BLOCKS  1184u         // 148 * 8, single wave
#define SP_THREADS 256u
#define NTHREADS   (SP_BLOCKS * SP_THREADS)   // 303104

__device__ float    g_part[SP_BLOCKS];
__device__ int      g_cntp[SP_BLOCKS];
__device__ unsigned g_done;              // ticket; reset by last block

__device__ __forceinline__ float gk(int i) {
    const float K0 = 2.6386456e-4f;
    const float K1 = 0.10645078f;
    const float K2 = 0.78657072f;
    return (i == 2) ? K2 : ((i == 1 || i == 3) ? K1 : K0);
}

__device__ __forceinline__ float sp2(float p) {   // log2(1 + exp(p))
    return __log2f(1.0f + __expf(p));
}

// prod *= (1 + exp(p))  ==  fma(prod, exp(p), prod)
__device__ __forceinline__ void pmul(float& pr, float p) {
    pr = fmaf(pr, __expf(p), pr);
}

__global__ __launch_bounds__(SP_THREADS, 8) void pitchloss_kernel(
    const float* __restrict__ preds, const int* __restrict__ gt,
    float* __restrict__ out)
{
    // ---- tu[up*8 + j]: target at window bin j (j<6) for code up in 0..4 ----
    __shared__ float tu[40];
    const int tid = threadIdx.x;
    if (tid < 40) {
        int up = tid >> 3, j = tid & 7;
        float t = 0.0f;
        if (j < 6) {
            if (up <= 2) {
                // exact low-edge rows: center q = up, bin n = j (c2 = 0)
                int q = up, n = j;
                #pragma unroll
                for (int i = 0; i < 5; i++) {
                    int m  = n + i - 2;
                    int mm = (m < 0) ? -m : ((m > NBINS - 1) ? (2*(NBINS-1) - m) : m);
                    if (mm == q) t += gk(i);
                }
            } else {
                // interior: center at window pos u = up - 1 (2 or 3)
                int ad = j - (up - 1); ad = (ad < 0) ? -ad : ad;
                t = (ad == 0) ? gk(2) : ((ad == 1) ? gk(1) : ((ad == 2) ? gk(0) : 0.0f));
            }
        }
        tu[tid] = t;
    }
    __syncthreads();

    const unsigned gtid = blockIdx.x * SP_THREADS + tid;

    // ---------------- phase A: per-row work --------------------------------
    float dot = 0.0f, neg = 0.0f;
    int   cnt = 0;
    for (unsigned r = gtid; r < ROWS; r += NTHREADS) {
        int g = gt[r];
        const float* row = preds + (size_t)r * NBINS;
        if (g != 100) {
            cnt++;
            int q  = (g > 50) ? min((g - 50) / 6, NBINS - 1) : 0;   // <= 24
            int c2 = (q >= 2) ? ((q - 2) >> 1) : 0;
            int up = (q <= 2) ? q : (3 + ((q - 2) & 1));
            const float2* w = reinterpret_cast<const float2*>(row) + c2;
            float2 a = __ldg(w);
            float2 b = __ldg(w + 1);
            float2 d = __ldg(w + 2);
            const float* tr = &tu[up * 8];
            dot = fmaf(a.x, tr[0], dot);
            dot = fmaf(a.y, tr[1], dot);
            dot = fmaf(b.x, tr[2], dot);
            dot = fmaf(b.y, tr[3], dot);
            dot = fmaf(d.x, tr[4], dot);
            dot = fmaf(d.y, tr[5], dot);
        } else {
            // rare (~0.5%): keep live set tiny -- do NOT unroll
            #pragma unroll 1
            for (int n = 0; n < NBINS; n++)
                neg += sp2(__ldg(row + n));
        }
    }

    // ---------------- phase B: streaming softplus over ALL elements -------
    const float4* p4 = reinterpret_cast<const float4*>(preds);
    float acc = 0.0f;
    unsigned i = gtid;
    for (; i + 3u * NTHREADS < NF4; i += 4u * NTHREADS) {
        float4 a = p4[i];
        float4 b = p4[i +      NTHREADS];
        float4 c = p4[i + 2u * NTHREADS];
        float4 d = p4[i + 3u * NTHREADS];
        float pr1 = 1.0f + __expf(a.x);
        pmul(pr1, a.y); pmul(pr1, a.z); pmul(pr1, a.w);
        pmul(pr1, b.x); pmul(pr1, b.y); pmul(pr1, b.z); pmul(pr1, b.w);
        float pr2 = 1.0f + __expf(c.x);
        pmul(pr2, c.y); pmul(pr2, c.z); pmul(pr2, c.w);
        pmul(pr2, d.x); pmul(pr2, d.y); pmul(pr2, d.z); pmul(pr2, d.w);
        acc += __log2f(pr1) + __log2f(pr2);
    }
    for (; i < NF4; i += NTHREADS) {
        float4 a = p4[i];
        float pr = 1.0f + __expf(a.x);
        pmul(pr, a.y); pmul(pr, a.z); pmul(pr, a.w);
        acc += __log2f(pr);
    }

    // ---------------- block reduction -------------------------------------
    const float LN2 = 0.69314718055994530942f;
    float part = fmaf(LN2, acc - neg, -dot);

    __shared__ float sp[SP_THREADS];
    __shared__ int   sc[SP_THREADS];
    sp[tid] = part; sc[tid] = cnt;
    __syncthreads();
    #pragma unroll
    for (int o = SP_THREADS / 2; o > 0; o >>= 1) {
        if (tid < o) { sp[tid] += sp[tid + o]; sc[tid] += sc[tid + o]; }
        __syncthreads();
    }

    __shared__ bool s_last;
    if (tid == 0) {
        g_part[blockIdx.x] = sp[0];
        g_cntp[blockIdx.x] = sc[0];
        __threadfence();
        unsigned t = atomicAdd(&g_done, 1u);
        s_last = (t == SP_BLOCKS - 1);
    }
    __syncthreads();

    // ---------------- last block: deterministic ordered finalize ----------
    if (s_last) {
        float a = 0.0f; int c = 0;
        for (unsigned j = tid; j < SP_BLOCKS; j += SP_THREADS) {
            a += g_part[j]; c += g_cntp[j];
        }
        sp[tid] = a; sc[tid] = c;
        __syncthreads();
        #pragma unroll
        for (int o = SP_THREADS / 2; o > 0; o >>= 1) {
            if (tid < o) { sp[tid] += sp[tid + o]; sc[tid] += sc[tid + o]; }
            __syncthreads();
        }
        if (tid == 0) {
            out[0] = sp[0] / (50.0f * (float)sc[0]);
            g_done = 0;   // reset for next (graph-replayed) launch
        }
    }
}

extern "C" void kernel_launch(void* const* d_in, const int* in_sizes, int n_in,
                              void* d_out, int out_size)
{
    const float* preds = (const float*)d_in[0];
    const int*   gt    = (const int*)d_in[1];
    float* out = (float*)d_out;

    pitchloss_kernel<<<SP_BLOCKS, SP_THREADS>>>(preds, gt, out);
}

// round 15
// speedup vs baseline: 1.4198x; 1.2205x over previous
#include <cuda_runtime.h>
#include <cuda_bf16.h>

// preds: [128, 4096, 50] float32 -> 26,214,400 elems (d_in[0])
// gt:    [128, 4096]     int32   ->    524,288 elems (d_in[1])
// out:   scalar float32
//
// loss = [ LN2*(sum_all log2(1+exp(p)) - sum_{unvoiced} log2(1+exp(p)))
//          - sum_{voiced} p.tgt ] / (50 * n_voiced)
//
// R6 champion restored verbatim (27.7us) -- every phase-A "improvement"
// (tables, float2 windows, warp spec, single-pass) regressed because the
// TIMED regime runs L2-resident (105MB < 126MB L2, no flush between graph
// replays): lean issue stream wins, smem/MIO-touching variants stall.
// Only change: grid 1184 -> 1216 (GB300 has 152 SMs; 152*8, one wave).

#define NF4       6553600u
#define ROWS      524288u
#define NBINS     50

#define SP_BLOCKS  1216u         // 152 * 8, single wave on GB300
#define SP_THREADS 256u
#define NTHREADS   (SP_BLOCKS * SP_THREADS)   // 311296

__device__ float    g_part[SP_BLOCKS];
__device__ int      g_cntp[SP_BLOCKS];
__device__ unsigned g_done;              // ticket; reset by last block

__device__ __forceinline__ float gk(int i) {
    const float K0 = 2.6386456e-4f;
    const float K1 = 0.10645078f;
    const float K2 = 0.78657072f;
    return (i == 2) ? K2 : ((i == 1 || i == 3) ? K1 : K0);
}

__device__ __forceinline__ float sp2(float p) {   // log2(1 + exp(p))
    return __log2f(1.0f + __expf(p));
}

// prod *= (1 + exp(p))  ==  fma(prod, exp(p), prod)
__device__ __forceinline__ void pmul(float& pr, float p) {
    pr = fmaf(pr, __expf(p), pr);
}

__global__ __launch_bounds__(SP_THREADS, 8) void pitchloss_kernel(
    const float* __restrict__ preds, const int* __restrict__ gt,
    float* __restrict__ out)
{
    const int      tid  = threadIdx.x;
    const unsigned gtid = blockIdx.x * SP_THREADS + tid;

    // ---------------- phase A: per-row work (voiced dot / unvoiced corr) --
    float dot = 0.0f, neg = 0.0f;
    int   cnt = 0;
    for (unsigned r = gtid; r < ROWS; r += NTHREADS) {
        int g = gt[r];
        const float* row = preds + (size_t)r * NBINS;
        if (g != 100) {
            cnt++;
            int q = (g > 50) ? min((g - 50) / 6, NBINS - 1) : 0;
            #pragma unroll
            for (int j = -2; j <= 2; j++) {
                int n = q + j;
                if (n < 0 || n > NBINS - 1) continue;
                float t = 0.0f;
                #pragma unroll
                for (int i2 = 0; i2 < 5; i2++) {
                    int m  = n + i2 - 2;
                    int mm = (m < 0) ? -m : ((m > NBINS - 1) ? (2*(NBINS-1) - m) : m);
                    if (mm == q) t += gk(i2);
                }
                dot = fmaf(__ldg(row + n), t, dot);
            }
        } else {
            #pragma unroll 5
            for (int n = 0; n < NBINS; n++)
                neg += sp2(__ldg(row + n));
        }
    }

    // ---------------- phase B: streaming softplus over ALL elements -------
    const float4* p4 = reinterpret_cast<const float4*>(preds);
    float acc = 0.0f;
    unsigned i = gtid;
    for (; i + 3u * NTHREADS < NF4; i += 4u * NTHREADS) {
        float4 a = p4[i];
        float4 b = p4[i +      NTHREADS];
        float4 c = p4[i + 2u * NTHREADS];
        float4 d = p4[i + 3u * NTHREADS];
        float pr1 = 1.0f + __expf(a.x);
        pmul(pr1, a.y); pmul(pr1, a.z); pmul(pr1, a.w);
        pmul(pr1, b.x); pmul(pr1, b.y); pmul(pr1, b.z); pmul(pr1, b.w);
        float pr2 = 1.0f + __expf(c.x);
        pmul(pr2, c.y); pmul(pr2, c.z); pmul(pr2, c.w);
        pmul(pr2, d.x); pmul(pr2, d.y); pmul(pr2, d.z); pmul(pr2, d.w);
        acc += __log2f(pr1) + __log2f(pr2);
    }
    for (; i < NF4; i += NTHREADS) {
        float4 a = p4[i];
        float pr = 1.0f + __expf(a.x);
        pmul(pr, a.y); pmul(pr, a.z); pmul(pr, a.w);
        acc += __log2f(pr);
    }

    // ---------------- block reduction -------------------------------------
    const float LN2 = 0.69314718055994530942f;
    float part = fmaf(LN2, acc - neg, -dot);

    __shared__ float sp[SP_THREADS];
    __shared__ int   sc[SP_THREADS];
    sp[tid] = part; sc[tid] = cnt;
    __syncthreads();
    #pragma unroll
    for (int o = SP_THREADS / 2; o > 0; o >>= 1) {
        if (tid < o) { sp[tid] += sp[tid + o]; sc[tid] += sc[tid + o]; }
        __syncthreads();
    }

    __shared__ bool s_last;
    if (tid == 0) {
        g_part[blockIdx.x] = sp[0];
        g_cntp[blockIdx.x] = sc[0];
        __threadfence();
        unsigned t = atomicAdd(&g_done, 1u);
        s_last = (t == SP_BLOCKS - 1);
    }
    __syncthreads();

    // ---------------- last block: deterministic ordered finalize ----------
    if (s_last) {
        float a = 0.0f; int c = 0;
        for (unsigned j = tid; j < SP_BLOCKS; j += SP_THREADS) {
            a += g_part[j]; c += g_cntp[j];
        }
        sp[tid] = a; sc[tid] = c;
        __syncthreads();
        #pragma unroll
        for (int o = SP_THREADS / 2; o > 0; o >>= 1) {
            if (tid < o) { sp[tid] += sp[tid + o]; sc[tid] += sc[tid + o]; }
            __syncthreads();
        }
        if (tid == 0) {
            out[0] = sp[0] / (50.0f * (float)sc[0]);
            g_done = 0;   // reset for next (graph-replayed) launch
        }
    }
}

extern "C" void kernel_launch(void* const* d_in, const int* in_sizes, int n_in,
                              void* d_out, int out_size)
{
    const float* preds = (const float*)d_in[0];
    const int*   gt    = (const int*)d_in[1];
    float* out = (float*)d_out;

    pitchloss_kernel<<<SP_BLOCKS, SP_THREADS>>>(preds, gt, out);
}